// round 8
// baseline (speedup 1.0000x reference)
#include <cuda_runtime.h>
#include <cuda_fp16.h>
#include <cstdint>
#include <cstddef>

// ---------------- problem constants ----------------
#define NE   100000      // entities
#define NRL  16          // relations
#define DIM  64
#define EE   1600000     // edges
#define PROJ_TILES 782   // ceil(NE/128)
#define SCAN_B 196       // ceil(NE/512)

// ---------------- device scratch (static: no runtime alloc allowed) -------
__device__ __align__(128) __half g_proj[(size_t)NRL * NE * DIM]; // 204.8 MB fp16
__device__ int   g_se[EE];          // src | (etype<<20)
__device__ int   g_dstv[EE];
__device__ float g_expv[EE];
__device__ float g_denom[NE];
__device__ int   g_deg[NE];
__device__ int   g_off[NE];
__device__ int   g_cur[NE];
__device__ int   g_part[SCAN_B];
__device__ int2  g_csr[EE];         // {src, bits(w)}
__device__ __align__(128) float g_h1[NE * DIM]; // un-normalized layer-0 out
__device__ int   g_is64;

__device__ __forceinline__ float tanhap(float x) {
    float y; asm("tanh.approx.f32 %0, %1;" : "=f"(y) : "f"(x)); return y;
}

// ================= K0: detect index dtype (int64 vs int32) ================
__global__ void k_detect(const void* srcp) {
    if (threadIdx.x == 0) {
        const long long* p = (const long long*)srcp;
        int ok = 1;
        for (int i = 0; i < 32; i++) {
            long long v = p[i];
            if (v < 0 || v >= NE) ok = 0;
        }
        g_is64 = ok;
    }
}

// ================= K1: prep (index pack, zeroing, out[:, :64] = ent) ======
__global__ void k_prep(const float* __restrict__ ent,
                       const void* __restrict__ srcp,
                       const void* __restrict__ dstp,
                       const void* __restrict__ etp,
                       float* __restrict__ out) {
    int gt = blockIdx.x * blockDim.x + threadIdx.x;
    int stp = gridDim.x * blockDim.x;
    int is64 = g_is64;
    if (is64) {
        const long long* s = (const long long*)srcp;
        const long long* d = (const long long*)dstp;
        const long long* e = (const long long*)etp;
        for (int i = gt; i < EE; i += stp) {
            g_se[i]   = (int)s[i] | ((int)e[i] << 20);
            g_dstv[i] = (int)d[i];
        }
    } else {
        const int* s = (const int*)srcp;
        const int* d = (const int*)dstp;
        const int* e = (const int*)etp;
        for (int i = gt; i < EE; i += stp) {
            g_se[i]   = s[i] | (e[i] << 20);
            g_dstv[i] = d[i];
        }
    }
    for (int i = gt; i < NE; i += stp) { g_denom[i] = 0.f; g_deg[i] = 0; }
    for (int i = gt; i < NE * DIM; i += stp)
        out[(size_t)(i >> 6) * 160 + (i & 63)] = ent[i];
}

// ================= K2: proj GEMM via mma.sync (f16 in, f32 acc) ===========
// proj[r,n,e] = sum_d ent[n,d] * W_R[r,d,e].  Block: 128 nodes, all 16 rel.
#define STRA 72
__global__ void __launch_bounds__(256) k_proj(const float* __restrict__ ent,
                                              const float* __restrict__ WR) {
    __shared__ __half sA[128 * STRA];   // ent tile  [row][k]
    __shared__ __half sB[64 * STRA];    // Wt tile   [n(e)][k(d)]
    int tid = threadIdx.x;
    int wid = tid >> 5, lane = tid & 31;
    int g = lane >> 2, tg = lane & 3;
    int row0 = blockIdx.x * 128;
    int m0 = wid * 16;

    // stage A (fp32 -> fp16)
    for (int i = tid; i < 128 * 64; i += 256) {
        int row = i >> 6, col = i & 63;
        int node = row0 + row;
        float v = (node < NE) ? ent[(size_t)node * 64 + col] : 0.f;
        sA[row * STRA + col] = __float2half(v);
    }

    for (int r = 0; r < NRL; r++) {
        __syncthreads();
        // stage B transposed: sB[e][d] = W_R[r][d][e]
        for (int i = tid; i < 4096; i += 256) {
            int d = i >> 6, e = i & 63;
            sB[e * STRA + d] = __float2half(WR[((size_t)r * 64 + d) * 64 + e]);
        }
        __syncthreads();

        float acc[8][4];
#pragma unroll
        for (int nt = 0; nt < 8; nt++)
#pragma unroll
            for (int j = 0; j < 4; j++) acc[nt][j] = 0.f;

#pragma unroll
        for (int kt = 0; kt < 4; kt++) {
            int k0 = kt * 16;
            const __half* pa = &sA[(m0 + g) * STRA + k0 + 2 * tg];
            uint32_t a0 = *(const uint32_t*)pa;
            uint32_t a1 = *(const uint32_t*)(pa + 8 * STRA);
            uint32_t a2 = *(const uint32_t*)(pa + 8);
            uint32_t a3 = *(const uint32_t*)(pa + 8 * STRA + 8);
#pragma unroll
            for (int nt = 0; nt < 8; nt++) {
                const __half* pb = &sB[(nt * 8 + g) * STRA + k0 + 2 * tg];
                uint32_t b0 = *(const uint32_t*)pb;
                uint32_t b1 = *(const uint32_t*)(pb + 8);
                asm volatile(
                    "mma.sync.aligned.m16n8k16.row.col.f32.f16.f16.f32 "
                    "{%0,%1,%2,%3},{%4,%5,%6,%7},{%8,%9},{%0,%1,%2,%3};\n"
                    : "+f"(acc[nt][0]), "+f"(acc[nt][1]),
                      "+f"(acc[nt][2]), "+f"(acc[nt][3])
                    : "r"(a0), "r"(a1), "r"(a2), "r"(a3), "r"(b0), "r"(b1));
            }
        }
        // epilogue: fp32 -> fp16, direct store
        int node_a = row0 + m0 + g;
        int node_b = node_a + 8;
        if (node_a < NE) {
            __half2* po = (__half2*)(g_proj + ((size_t)r * NE + node_a) * 64);
#pragma unroll
            for (int nt = 0; nt < 8; nt++)
                po[nt * 4 + tg] = __floats2half2_rn(acc[nt][0], acc[nt][1]);
        }
        if (node_b < NE) {
            __half2* po = (__half2*)(g_proj + ((size_t)r * NE + node_b) * 64);
#pragma unroll
            for (int nt = 0; nt < 8; nt++)
                po[nt * 4 + tg] = __floats2half2_rn(acc[nt][2], acc[nt][3]);
        }
    }
}

// ================= K3: attention scores: e=exp(att), denom, degree ========
// 8 lanes per edge; 32 edges per block of 256 threads.
__global__ void __launch_bounds__(256) k_att(const float* __restrict__ rel) {
    __shared__ float sRel[NRL * DIM];
    int tid = threadIdx.x;
    for (int i = tid; i < NRL * DIM; i += 256) sRel[i] = rel[i];
    __syncthreads();

    int e = blockIdx.x * 32 + (tid >> 3);
    int lane8 = tid & 7;
    int se = g_se[e];
    int s = se & 0xFFFFF;
    int r = se >> 20;
    int d = g_dstv[e];

    const uint4* tp = (const uint4*)(g_proj + ((size_t)r * NE + s) * 64);
    const uint4* hp = (const uint4*)(g_proj + ((size_t)r * NE + d) * 64);
    uint4 t4 = tp[lane8];
    uint4 h4 = hp[lane8];
    const float* rl = &sRel[r * 64 + lane8 * 8];

    float att = 0.f;
    const uint32_t* tw = (const uint32_t*)&t4;
    const uint32_t* hw = (const uint32_t*)&h4;
#pragma unroll
    for (int j = 0; j < 4; j++) {
        float2 tf = __half22float2(*(const __half2*)&tw[j]);
        float2 hf = __half22float2(*(const __half2*)&hw[j]);
        att += tf.x * tanhap(hf.x + rl[2 * j]);
        att += tf.y * tanhap(hf.y + rl[2 * j + 1]);
    }
    att += __shfl_xor_sync(0xFFFFFFFF, att, 4);
    att += __shfl_xor_sync(0xFFFFFFFF, att, 2);
    att += __shfl_xor_sync(0xFFFFFFFF, att, 1);

    if (lane8 == 0) {
        float ev = __expf(att);      // |att| small: no max-shift needed
        g_expv[e] = ev;
        atomicAdd(&g_denom[d], ev);
        atomicAdd(&g_deg[d], 1);
    }
}

// ================= K4-6: exclusive scan of degrees ========================
__global__ void k_scan1() {
    __shared__ int sm[512];
    int tid = threadIdx.x;
    int i = blockIdx.x * 512 + tid;
    int x = (i < NE) ? g_deg[i] : 0;
    sm[tid] = x;
    for (int o = 1; o < 512; o <<= 1) {
        __syncthreads();
        int t = (tid >= o) ? sm[tid - o] : 0;
        __syncthreads();
        sm[tid] += t;
    }
    __syncthreads();
    if (i < NE) g_off[i] = sm[tid] - x;        // block-local exclusive
    if (tid == 511) g_part[blockIdx.x] = sm[511];
}
__global__ void k_scan2() {
    if (threadIdx.x == 0) {
        int run = 0;
        for (int b = 0; b < SCAN_B; b++) {
            int t = g_part[b]; g_part[b] = run; run += t;
        }
    }
}
__global__ void k_scan3() {
    int i = blockIdx.x * 512 + threadIdx.x;
    if (i < NE) {
        int o = g_off[i] + g_part[blockIdx.x];
        g_off[i] = o;
        g_cur[i] = o;
    }
}

// ================= K7: scatter edges into dst-CSR with softmax weight =====
__global__ void __launch_bounds__(256) k_scatter() {
    int e = blockIdx.x * 256 + threadIdx.x;
    int d = g_dstv[e];
    int p = atomicAdd(&g_cur[d], 1);
    float w = g_expv[e] / g_denom[d];
    g_csr[p] = make_int2(g_se[e] & 0xFFFFF, __float_as_int(w));
}

// ================= K8: fused KGAT layer (agg + bi-mul + GEMV + lrelu + l2) =
template <int OUT>
__global__ void __launch_bounds__(256) k_layer(const float* __restrict__ hin,
                                               const float* __restrict__ W,
                                               float* __restrict__ hraw,
                                               float* __restrict__ out,
                                               int col0) {
    __shared__ float sW[64 * OUT];
    __shared__ float sv[8][64];
    int tid = threadIdx.x;
    for (int i = tid; i < 64 * OUT; i += 256) sW[i] = W[i];
    __syncthreads();

    int wid = tid >> 5, lane = tid & 31;
    int n = blockIdx.x * 8 + wid;          // grid exactly 12500 -> n < NE

    float h0 = hin[(size_t)n * 64 + lane];
    float h1 = hin[(size_t)n * 64 + 32 + lane];
    int beg = g_off[n];
    int cnt = g_deg[n];

    float a0 = 0.f, a1 = 0.f;
    for (int base = 0; base < cnt; base += 32) {
        int m = cnt - base; if (m > 32) m = 32;
        int2 ew = (lane < m) ? g_csr[beg + base + lane] : make_int2(0, 0);
        for (int j = 0; j < m; j++) {
            int   s = __shfl_sync(0xFFFFFFFF, ew.x, j);
            float w = __int_as_float(__shfl_sync(0xFFFFFFFF, ew.y, j));
            a0 = fmaf(w, hin[(size_t)s * 64 + lane], a0);
            a1 = fmaf(w, hin[(size_t)s * 64 + 32 + lane], a1);
        }
    }
    sv[wid][lane]      = h0 * a0;
    sv[wid][lane + 32] = h1 * a1;
    __syncwarp();

    if (OUT == 64) {
        float o0 = 0.f, o1 = 0.f;
#pragma unroll 8
        for (int k = 0; k < 64; k++) {
            float vk = sv[wid][k];
            o0 = fmaf(vk, sW[k * 64 + lane], o0);
            o1 = fmaf(vk, sW[k * 64 + lane + 32], o1);
        }
        o0 = (o0 > 0.f) ? o0 : 0.01f * o0;
        o1 = (o1 > 0.f) ? o1 : 0.01f * o1;
        hraw[(size_t)n * 64 + lane]      = o0;
        hraw[(size_t)n * 64 + 32 + lane] = o1;
        float ss = o0 * o0 + o1 * o1;
#pragma unroll
        for (int o = 16; o; o >>= 1) ss += __shfl_xor_sync(0xFFFFFFFF, ss, o);
        float sc = 1.f / fmaxf(sqrtf(ss), 1e-12f);
        out[(size_t)n * 160 + col0 + lane]      = o0 * sc;
        out[(size_t)n * 160 + col0 + 32 + lane] = o1 * sc;
    } else {
        float o0 = 0.f;
#pragma unroll 8
        for (int k = 0; k < 64; k++)
            o0 = fmaf(sv[wid][k], sW[k * 32 + lane], o0);
        o0 = (o0 > 0.f) ? o0 : 0.01f * o0;
        float ss = o0 * o0;
#pragma unroll
        for (int o = 16; o; o >>= 1) ss += __shfl_xor_sync(0xFFFFFFFF, ss, o);
        float sc = 1.f / fmaxf(sqrtf(ss), 1e-12f);
        out[(size_t)n * 160 + col0 + lane] = o0 * sc;
    }
}

// ================= launch =================================================
extern "C" void kernel_launch(void* const* d_in, const int* in_sizes, int n_in,
                              void* d_out, int out_size) {
    const float* ent = (const float*)d_in[0];   // [NE, 64]
    const float* rel = (const float*)d_in[1];   // [16, 64]
    const float* WR  = (const float*)d_in[2];   // [16, 64, 64]
    const float* W0  = (const float*)d_in[3];   // [64, 64]
    const float* W1  = (const float*)d_in[4];   // [64, 32]
    const void*  src = d_in[5];
    const void*  dst = d_in[6];
    const void*  et  = d_in[7];
    float* out = (float*)d_out;                 // [NE, 160]

    float* h1raw;
    cudaGetSymbolAddress((void**)&h1raw, g_h1);

    k_detect<<<1, 32>>>(src);
    k_prep<<<512, 256>>>(ent, src, dst, et, out);
    k_proj<<<PROJ_TILES, 256>>>(ent, WR);
    k_att<<<EE / 32, 256>>>(rel);
    k_scan1<<<SCAN_B, 512>>>();
    k_scan2<<<1, 32>>>();
    k_scan3<<<SCAN_B, 512>>>();
    k_scatter<<<EE / 256, 256>>>();
    k_layer<64><<<NE / 8, 256>>>(ent,   W0, h1raw, out, 64);
    k_layer<32><<<NE / 8, 256>>>(h1raw, W1, h1raw, out, 128);
}